// round 7
// baseline (speedup 1.0000x reference)
#include <cuda_runtime.h>
#include <cuda_fp16.h>
#include <cstdint>

#define N_NODES 100000
#define NFEAT   256
#define NHID    128
#define NHID2   64

// Scratch (no cudaMalloc allowed). H0/H2 stored as fp16 (halves gather bytes).
__device__ __half g_H0h[(size_t)N_NODES * NHID];   // fp16(x @ W1)
__device__ float  g_H1[(size_t)N_NODES * NHID];    // relu(spmm(A,H0)+b1)  fp32
__device__ __half g_H2h[(size_t)N_NODES * NHID2];  // fp16(H1 @ W2)
__device__ int    g_rowptr[N_NODES + 1];

// ---------------------------------------------------------------------------
// row_ptr from sorted COO rows: rp[i] = lower_bound(rows, i)
// ---------------------------------------------------------------------------
__global__ void rowptr_kernel(const int* __restrict__ rows, int E,
                              int* __restrict__ rp) {
    int i = blockIdx.x * blockDim.x + threadIdx.x;
    if (i > N_NODES) return;
    int lo = 0, hi = E;
    while (lo < hi) {
        int mid = (lo + hi) >> 1;
        if (rows[mid] < i) lo = mid + 1; else hi = mid;
    }
    rp[i] = lo;
}

// ---------------------------------------------------------------------------
// TF32 helpers (3xTF32 split for ~fp32 accuracy on tensor cores)
// ---------------------------------------------------------------------------
__device__ __forceinline__ void split_tf32(float x, uint32_t& hi, uint32_t& lo) {
    asm("cvt.rna.tf32.f32 %0, %1;" : "=r"(hi) : "f"(x));
    float hif = __uint_as_float(hi);
    float lof = x - hif;
    asm("cvt.rna.tf32.f32 %0, %1;" : "=r"(lo) : "f"(lof));
}

__device__ __forceinline__ void mma_tf32(float* d, const uint32_t* a,
                                         const uint32_t* b) {
    asm("mma.sync.aligned.m16n8k8.row.col.f32.tf32.tf32.f32 "
        "{%0,%1,%2,%3},{%4,%5,%6,%7},{%8,%9},{%0,%1,%2,%3};"
        : "+f"(d[0]), "+f"(d[1]), "+f"(d[2]), "+f"(d[3])
        : "r"(a[0]), "r"(a[1]), "r"(a[2]), "r"(a[3]), "r"(b[0]), "r"(b[1]));
}

// ---------------------------------------------------------------------------
// Tensor-core GEMM (R3 mainloop, measured 43us for M=100k,N=128,K=256).
// HALF_OUT: epilogue converts to fp16 and stores __half2 (for SpMM gathers).
// ---------------------------------------------------------------------------
#define GBM 128
#define GBN 64
#define GBK 32

template <bool HALF_OUT>
__global__ __launch_bounds__(256) void gemm_tf32_kernel(
    const float* __restrict__ A, const float* __restrict__ B,
    void* __restrict__ Cv, int M, int N, int K) {
    __shared__ float As[GBM][GBK + 4];
    __shared__ float Bs[GBK][GBN + 4];

    const int tid  = threadIdx.x;
    const int wid  = tid >> 5, lane = tid & 31;
    const int g    = lane >> 2, tig = lane & 3;
    const int warp_m = wid >> 1, warp_n = wid & 1;
    const int mBase = blockIdx.x * GBM;
    const int nBase = blockIdx.y * GBN;
    const int KT = K / GBK;

    float acc[2][4][4];
#pragma unroll
    for (int mi = 0; mi < 2; mi++)
#pragma unroll
        for (int ni = 0; ni < 4; ni++)
#pragma unroll
            for (int r = 0; r < 4; r++) acc[mi][ni][r] = 0.f;

    float4 aReg[4], bReg[2];

    auto loadTile = [&](int kt) {
#pragma unroll
        for (int i = 0; i < 4; i++) {
            int idx = tid + i * 256;
            int row = idx >> 3, kc = (idx & 7) << 2;
            int grow = mBase + row;
            float4 v = make_float4(0.f, 0.f, 0.f, 0.f);
            if (grow < M)
                v = *reinterpret_cast<const float4*>(
                        &A[(size_t)grow * K + kt * GBK + kc]);
            aReg[i] = v;
        }
#pragma unroll
        for (int i = 0; i < 2; i++) {
            int idx = tid + i * 256;
            int kr = idx >> 4, nc = (idx & 15) << 2;
            bReg[i] = *reinterpret_cast<const float4*>(
                          &B[(size_t)(kt * GBK + kr) * N + nBase + nc]);
        }
    };
    auto stageTile = [&]() {
#pragma unroll
        for (int i = 0; i < 4; i++) {
            int idx = tid + i * 256;
            int row = idx >> 3, kc = (idx & 7) << 2;
            *reinterpret_cast<float4*>(&As[row][kc]) = aReg[i];
        }
#pragma unroll
        for (int i = 0; i < 2; i++) {
            int idx = tid + i * 256;
            int kr = idx >> 4, nc = (idx & 15) << 2;
            *reinterpret_cast<float4*>(&Bs[kr][nc]) = bReg[i];
        }
    };

    loadTile(0);
    stageTile();
    __syncthreads();

    for (int kt = 0; kt < KT; kt++) {
        if (kt + 1 < KT) loadTile(kt + 1);

#pragma unroll
        for (int ka = 0; ka < 4; ka++) {
            uint32_t ah[2][4], al[2][4], bh[4][2], bl[4][2];
#pragma unroll
            for (int mi = 0; mi < 2; mi++) {
                int row = warp_m * 32 + mi * 16 + g;
                int k0 = ka * 8 + tig;
                split_tf32(As[row][k0],       ah[mi][0], al[mi][0]);
                split_tf32(As[row + 8][k0],   ah[mi][1], al[mi][1]);
                split_tf32(As[row][k0 + 4],   ah[mi][2], al[mi][2]);
                split_tf32(As[row + 8][k0+4], ah[mi][3], al[mi][3]);
            }
#pragma unroll
            for (int ni = 0; ni < 4; ni++) {
                int col = warp_n * 32 + ni * 8 + g;
                split_tf32(Bs[ka * 8 + tig][col],     bh[ni][0], bl[ni][0]);
                split_tf32(Bs[ka * 8 + tig + 4][col], bh[ni][1], bl[ni][1]);
            }
#pragma unroll
            for (int mi = 0; mi < 2; mi++)
#pragma unroll
                for (int ni = 0; ni < 4; ni++) {
                    mma_tf32(acc[mi][ni], ah[mi], bh[ni]);
                    mma_tf32(acc[mi][ni], ah[mi], bl[ni]);
                    mma_tf32(acc[mi][ni], al[mi], bh[ni]);
                }
        }
        __syncthreads();
        if (kt + 1 < KT) {
            stageTile();
            __syncthreads();
        }
    }

    // store
#pragma unroll
    for (int mi = 0; mi < 2; mi++) {
        int row = mBase + warp_m * 32 + mi * 16 + g;
#pragma unroll
        for (int ni = 0; ni < 4; ni++) {
            int col = nBase + warp_n * 32 + ni * 8 + 2 * tig;
            if (HALF_OUT) {
                __half* C16 = (__half*)Cv;
                if (row < M)
                    *reinterpret_cast<__half2*>(&C16[(size_t)row * N + col]) =
                        __floats2half2_rn(acc[mi][ni][0], acc[mi][ni][1]);
                if (row + 8 < M)
                    *reinterpret_cast<__half2*>(&C16[(size_t)(row + 8) * N + col]) =
                        __floats2half2_rn(acc[mi][ni][2], acc[mi][ni][3]);
            } else {
                float* C = (float*)Cv;
                if (row < M)
                    *reinterpret_cast<float2*>(&C[(size_t)row * N + col]) =
                        make_float2(acc[mi][ni][0], acc[mi][ni][1]);
                if (row + 8 < M)
                    *reinterpret_cast<float2*>(&C[(size_t)(row + 8) * N + col]) =
                        make_float2(acc[mi][ni][2], acc[mi][ni][3]);
            }
        }
    }
}

// ---------------------------------------------------------------------------
// CSR SpMM, warp per node, EDGE-PAIRED gathers:
// lanes 0-15 process edge i, lanes 16-31 edge i+1; each lane loads 16B (uint4)
// of the fp16 H row -> one LDG.128 covers 2 edges (512B in flight).
// Metadata (int4/float4 per 4 edges) software-pipelined one iteration ahead.
// Partials folded with shfl_xor(16); fused bias+ReLU on store.
// F=128: lane sub owns 8 features. fp32 accumulate.
// ---------------------------------------------------------------------------
#define FULLMASK 0xFFFFFFFFu

__global__ __launch_bounds__(256) void spmm_f16_128(
    const float* __restrict__ vals, const int* __restrict__ cols,
    const int* __restrict__ rp, const uint4* __restrict__ Hv,
    const float4* __restrict__ bias4, float4* __restrict__ out4) {
    int node = blockIdx.x * 8 + (threadIdx.x >> 5);
    int lane = threadIdx.x & 31;
    if (node >= N_NODES) return;
    int s = rp[node], e = rp[node + 1];
    int half = lane >> 4, sub = lane & 15;

    float acc[8];
#pragma unroll
    for (int j = 0; j < 8; j++) acc[j] = 0.f;

    auto gatherAcc = [&](int c, float v) {
        uint4 u = __ldg(&Hv[(size_t)c * 16 + sub]);
        const __half2* hp = reinterpret_cast<const __half2*>(&u);
#pragma unroll
        for (int j = 0; j < 4; j++) {
            float2 f = __half22float2(hp[j]);
            acc[2 * j]     = fmaf(v, f.x, acc[2 * j]);
            acc[2 * j + 1] = fmaf(v, f.y, acc[2 * j + 1]);
        }
    };

    int i = s;
    // head to 16B alignment (scalar edges: half 1 contributes zero)
    for (; i < e && (i & 3); i++) {
        int   c = __ldg(&cols[i]);
        float v = half ? 0.f : __ldg(&vals[i]);
        gatherAcc(c, v);
    }
    // pipelined body: 4 edges / iter, metadata prefetched one iter ahead
    if (i + 4 <= e) {
        int4   c4 = __ldg(reinterpret_cast<const int4*>(&cols[i]));
        float4 v4 = __ldg(reinterpret_cast<const float4*>(&vals[i]));
        for (;;) {
            int inext = i + 4;
            bool more = (inext + 4 <= e);
            int4 c4n; float4 v4n;
            if (more) {
                c4n = __ldg(reinterpret_cast<const int4*>(&cols[inext]));
                v4n = __ldg(reinterpret_cast<const float4*>(&vals[inext]));
            }
            // pair 0: edges i (half 0), i+1 (half 1)
            gatherAcc(half ? c4.y : c4.x, half ? v4.y : v4.x);
            // pair 1: edges i+2 (half 0), i+3 (half 1)
            gatherAcc(half ? c4.w : c4.z, half ? v4.w : v4.z);
            i = inext;
            if (!more) break;
            c4 = c4n; v4 = v4n;
        }
    }
    // tail
    for (; i < e; i++) {
        int   c = __ldg(&cols[i]);
        float v = half ? 0.f : __ldg(&vals[i]);
        gatherAcc(c, v);
    }

    // fold the two half-warps
#pragma unroll
    for (int j = 0; j < 8; j++)
        acc[j] += __shfl_xor_sync(FULLMASK, acc[j], 16);

    if (half == 0) {
        float4 b0 = bias4[sub * 2], b1 = bias4[sub * 2 + 1];
        float4 o0 = make_float4(fmaxf(acc[0] + b0.x, 0.f),
                                fmaxf(acc[1] + b0.y, 0.f),
                                fmaxf(acc[2] + b0.z, 0.f),
                                fmaxf(acc[3] + b0.w, 0.f));
        float4 o1 = make_float4(fmaxf(acc[4] + b1.x, 0.f),
                                fmaxf(acc[5] + b1.y, 0.f),
                                fmaxf(acc[6] + b1.z, 0.f),
                                fmaxf(acc[7] + b1.w, 0.f));
        out4[(size_t)node * 32 + sub * 2]     = o0;
        out4[(size_t)node * 32 + sub * 2 + 1] = o1;
    }
}

// F=64: lane sub owns 4 features (uint2 = 8B per gather), same pairing.
__global__ __launch_bounds__(256) void spmm_f16_64(
    const float* __restrict__ vals, const int* __restrict__ cols,
    const int* __restrict__ rp, const uint2* __restrict__ Hv,
    const float4* __restrict__ bias4, float4* __restrict__ out4) {
    int node = blockIdx.x * 8 + (threadIdx.x >> 5);
    int lane = threadIdx.x & 31;
    if (node >= N_NODES) return;
    int s = rp[node], e = rp[node + 1];
    int half = lane >> 4, sub = lane & 15;

    float acc[4];
#pragma unroll
    for (int j = 0; j < 4; j++) acc[j] = 0.f;

    auto gatherAcc = [&](int c, float v) {
        uint2 u = __ldg(&Hv[(size_t)c * 16 + sub]);
        float2 f0 = __half22float2(*reinterpret_cast<const __half2*>(&u.x));
        float2 f1 = __half22float2(*reinterpret_cast<const __half2*>(&u.y));
        acc[0] = fmaf(v, f0.x, acc[0]);
        acc[1] = fmaf(v, f0.y, acc[1]);
        acc[2] = fmaf(v, f1.x, acc[2]);
        acc[3] = fmaf(v, f1.y, acc[3]);
    };

    int i = s;
    for (; i < e && (i & 3); i++) {
        int   c = __ldg(&cols[i]);
        float v = half ? 0.f : __ldg(&vals[i]);
        gatherAcc(c, v);
    }
    if (i + 4 <= e) {
        int4   c4 = __ldg(reinterpret_cast<const int4*>(&cols[i]));
        float4 v4 = __ldg(reinterpret_cast<const float4*>(&vals[i]));
        for (;;) {
            int inext = i + 4;
            bool more = (inext + 4 <= e);
            int4 c4n; float4 v4n;
            if (more) {
                c4n = __ldg(reinterpret_cast<const int4*>(&cols[inext]));
                v4n = __ldg(reinterpret_cast<const float4*>(&vals[inext]));
            }
            gatherAcc(half ? c4.y : c4.x, half ? v4.y : v4.x);
            gatherAcc(half ? c4.w : c4.z, half ? v4.w : v4.z);
            i = inext;
            if (!more) break;
            c4 = c4n; v4 = v4n;
        }
    }
    for (; i < e; i++) {
        int   c = __ldg(&cols[i]);
        float v = half ? 0.f : __ldg(&vals[i]);
        gatherAcc(c, v);
    }

#pragma unroll
    for (int j = 0; j < 4; j++)
        acc[j] += __shfl_xor_sync(FULLMASK, acc[j], 16);

    if (half == 0) {
        float4 b = bias4[sub];
        float4 o = make_float4(fmaxf(acc[0] + b.x, 0.f),
                               fmaxf(acc[1] + b.y, 0.f),
                               fmaxf(acc[2] + b.z, 0.f),
                               fmaxf(acc[3] + b.w, 0.f));
        out4[(size_t)node * 16 + sub] = o;
    }
}

// ---------------------------------------------------------------------------
extern "C" void kernel_launch(void* const* d_in, const int* in_sizes, int n_in,
                              void* d_out, int out_size) {
    const float* x     = (const float*)d_in[0];
    const float* W1    = (const float*)d_in[1];
    const float* b1    = (const float*)d_in[2];
    const float* W2    = (const float*)d_in[3];
    const float* b2    = (const float*)d_in[4];
    const float* evals = (const float*)d_in[5];
    const int*   erows = (const int*)d_in[6];
    const int*   ecols = (const int*)d_in[7];
    float*       out   = (float*)d_out;

    const int E = in_sizes[5];

    void *pH0, *pH1, *pH2, *pRP;
    cudaGetSymbolAddress(&pH0, g_H0h);
    cudaGetSymbolAddress(&pH1, g_H1);
    cudaGetSymbolAddress(&pH2, g_H2h);
    cudaGetSymbolAddress(&pRP, g_rowptr);
    __half* H0h = (__half*)pH0;
    float*  H1  = (float*)pH1;
    __half* H2h = (__half*)pH2;
    int*    rp  = (int*)pRP;

    const int SPMM_GRID = (N_NODES + 7) / 8;

    // row_ptr from sorted rows
    rowptr_kernel<<<(N_NODES + 1 + 255) / 256, 256>>>(erows, E, rp);

    // GEMM1: H0h = fp16(x @ W1)   (M=100000, N=128, K=256)
    {
        dim3 grid((N_NODES + GBM - 1) / GBM, NHID / GBN);
        gemm_tf32_kernel<true><<<grid, 256>>>(x, W1, H0h, N_NODES, NHID, NFEAT);
    }

    // SpMM1: H1 = relu(A @ H0 + b1)
    spmm_f16_128<<<SPMM_GRID, 256>>>(evals, ecols, rp, (const uint4*)H0h,
                                     (const float4*)b1, (float4*)H1);

    // GEMM2: H2h = fp16(H1 @ W2)   (M=100000, N=64, K=128)
    {
        dim3 grid((N_NODES + GBM - 1) / GBM, NHID2 / GBN);
        gemm_tf32_kernel<true><<<grid, 256>>>(H1, W2, H2h, N_NODES, NHID2, NHID);
    }

    // SpMM2: out = relu(A @ H2 + b2)
    spmm_f16_64<<<SPMM_GRID, 256>>>(evals, ecols, rp, (const uint2*)H2h,
                                    (const float4*)b2, (float4*)out);
}

// round 8
// speedup vs baseline: 1.5466x; 1.5466x over previous
#include <cuda_runtime.h>
#include <cuda_fp16.h>
#include <cstdint>

#define N_NODES 100000
#define NFEAT   256
#define NHID    128
#define NHID2   64

// Scratch (no cudaMalloc allowed). H0/H2 stored as fp16 (halves gather bytes).
__device__ __half g_H0h[(size_t)N_NODES * NHID];   // fp16(x @ W1)
__device__ float  g_H1[(size_t)N_NODES * NHID];    // relu(spmm(A,H0)+b1)  fp32
__device__ __half g_H2h[(size_t)N_NODES * NHID2];  // fp16(H1 @ W2)
__device__ int    g_rowptr[N_NODES + 1];

// ---------------------------------------------------------------------------
// row_ptr from sorted COO rows: rp[i] = lower_bound(rows, i)
// ---------------------------------------------------------------------------
__global__ void rowptr_kernel(const int* __restrict__ rows, int E,
                              int* __restrict__ rp) {
    int i = blockIdx.x * blockDim.x + threadIdx.x;
    if (i > N_NODES) return;
    int lo = 0, hi = E;
    while (lo < hi) {
        int mid = (lo + hi) >> 1;
        if (rows[mid] < i) lo = mid + 1; else hi = mid;
    }
    rp[i] = lo;
}

// ---------------------------------------------------------------------------
// fp16 tensor-core GEMM: C = A @ B, fp32 in (converted to fp16 at staging),
// fp32 accumulate. mma.m16n8k16. Tile BM=128 x BN=64, BK=32, 256 threads,
// warps 4(m) x 2(n), each warp computes 32x32.
// As: [GBM][APITCH] halves row-major-in-k; Bst: [GBN][BPITCH] halves
// (B transposed at staging so k is contiguous). APITCH=BPITCH=40 halves
// -> LDS word index row*20+t covers all 32 banks, conflict-free.
// HALF_OUT: store fp16 (for SpMM gathers), else fp32.
// ---------------------------------------------------------------------------
#define GBM 128
#define GBN 64
#define GBK 32
#define HPITCH 40

__device__ __forceinline__ void mma_f16(float* d, const uint32_t* a,
                                        const uint32_t* b) {
    asm("mma.sync.aligned.m16n8k16.row.col.f32.f16.f16.f32 "
        "{%0,%1,%2,%3},{%4,%5,%6,%7},{%8,%9},{%0,%1,%2,%3};"
        : "+f"(d[0]), "+f"(d[1]), "+f"(d[2]), "+f"(d[3])
        : "r"(a[0]), "r"(a[1]), "r"(a[2]), "r"(a[3]), "r"(b[0]), "r"(b[1]));
}

template <bool HALF_OUT>
__global__ __launch_bounds__(256) void gemm_f16_kernel(
    const float* __restrict__ A, const float* __restrict__ B,
    void* __restrict__ Cv, int M, int N, int K) {
    __shared__ __half As[GBM * HPITCH];
    __shared__ __half Bst[GBN * HPITCH];

    const int tid  = threadIdx.x;
    const int wid  = tid >> 5, lane = tid & 31;
    const int g    = lane >> 2, tig = lane & 3;
    const int warp_m = wid >> 1, warp_n = wid & 1;
    const int mBase = blockIdx.x * GBM;
    const int nBase = blockIdx.y * GBN;
    const int KT = K / GBK;

    float acc[2][4][4];
#pragma unroll
    for (int mi = 0; mi < 2; mi++)
#pragma unroll
        for (int ni = 0; ni < 4; ni++)
#pragma unroll
            for (int r = 0; r < 4; r++) acc[mi][ni][r] = 0.f;

    float4 aReg[4], bReg[2];

    auto loadTile = [&](int kt) {
#pragma unroll
        for (int i = 0; i < 4; i++) {
            int idx = tid + i * 256;
            int row = idx >> 3, kc = (idx & 7) << 2;
            int grow = mBase + row;
            float4 v = make_float4(0.f, 0.f, 0.f, 0.f);
            if (grow < M)
                v = *reinterpret_cast<const float4*>(
                        &A[(size_t)grow * K + kt * GBK + kc]);
            aReg[i] = v;
        }
#pragma unroll
        for (int i = 0; i < 2; i++) {
            int idx = tid + i * 256;
            int kr = idx >> 4, nc = (idx & 15) << 2;
            bReg[i] = *reinterpret_cast<const float4*>(
                          &B[(size_t)(kt * GBK + kr) * N + nBase + nc]);
        }
    };
    auto stageTile = [&]() {
        // A: row-major in k, 4 contiguous halves per thread-chunk (8B store)
#pragma unroll
        for (int i = 0; i < 4; i++) {
            int idx = tid + i * 256;
            int row = idx >> 3, kc = (idx & 7) << 2;
            float4 v = aReg[i];
            __half2 h01 = __floats2half2_rn(v.x, v.y);
            __half2 h23 = __floats2half2_rn(v.z, v.w);
            uint2 pk = make_uint2(*reinterpret_cast<uint32_t*>(&h01),
                                  *reinterpret_cast<uint32_t*>(&h23));
            *reinterpret_cast<uint2*>(&As[row * HPITCH + kc]) = pk;
        }
        // B: transpose to [n][k] halves (4 scalar stores per float4)
#pragma unroll
        for (int i = 0; i < 2; i++) {
            int idx = tid + i * 256;
            int kr = idx >> 4, nc = (idx & 15) << 2;
            float4 v = bReg[i];
            Bst[(nc + 0) * HPITCH + kr] = __float2half_rn(v.x);
            Bst[(nc + 1) * HPITCH + kr] = __float2half_rn(v.y);
            Bst[(nc + 2) * HPITCH + kr] = __float2half_rn(v.z);
            Bst[(nc + 3) * HPITCH + kr] = __float2half_rn(v.w);
        }
    };

    loadTile(0);
    stageTile();
    __syncthreads();

    for (int kt = 0; kt < KT; kt++) {
        if (kt + 1 < KT) loadTile(kt + 1);

#pragma unroll
        for (int ka = 0; ka < 2; ka++) {            // two k16 chunks per BK=32
            const int k0 = ka * 16 + 2 * tig;
            uint32_t a[2][4], b[4][2];
#pragma unroll
            for (int mi = 0; mi < 2; mi++) {
                int row = warp_m * 32 + mi * 16 + g;
                a[mi][0] = *reinterpret_cast<const uint32_t*>(&As[row * HPITCH + k0]);
                a[mi][1] = *reinterpret_cast<const uint32_t*>(&As[(row + 8) * HPITCH + k0]);
                a[mi][2] = *reinterpret_cast<const uint32_t*>(&As[row * HPITCH + k0 + 8]);
                a[mi][3] = *reinterpret_cast<const uint32_t*>(&As[(row + 8) * HPITCH + k0 + 8]);
            }
#pragma unroll
            for (int ni = 0; ni < 4; ni++) {
                int col = warp_n * 32 + ni * 8 + g;
                b[ni][0] = *reinterpret_cast<const uint32_t*>(&Bst[col * HPITCH + k0]);
                b[ni][1] = *reinterpret_cast<const uint32_t*>(&Bst[col * HPITCH + k0 + 8]);
            }
#pragma unroll
            for (int mi = 0; mi < 2; mi++)
#pragma unroll
                for (int ni = 0; ni < 4; ni++)
                    mma_f16(acc[mi][ni], a[mi], b[ni]);
        }
        __syncthreads();
        if (kt + 1 < KT) {
            stageTile();
            __syncthreads();
        }
    }

    // store (same accumulator layout as m16n8k8 f32)
#pragma unroll
    for (int mi = 0; mi < 2; mi++) {
        int row = mBase + warp_m * 32 + mi * 16 + g;
#pragma unroll
        for (int ni = 0; ni < 4; ni++) {
            int col = nBase + warp_n * 32 + ni * 8 + 2 * tig;
            if (HALF_OUT) {
                __half* C16 = (__half*)Cv;
                if (row < M)
                    *reinterpret_cast<__half2*>(&C16[(size_t)row * N + col]) =
                        __floats2half2_rn(acc[mi][ni][0], acc[mi][ni][1]);
                if (row + 8 < M)
                    *reinterpret_cast<__half2*>(&C16[(size_t)(row + 8) * N + col]) =
                        __floats2half2_rn(acc[mi][ni][2], acc[mi][ni][3]);
            } else {
                float* C = (float*)Cv;
                if (row < M)
                    *reinterpret_cast<float2*>(&C[(size_t)row * N + col]) =
                        make_float2(acc[mi][ni][0], acc[mi][ni][1]);
                if (row + 8 < M)
                    *reinterpret_cast<float2*>(&C[(size_t)(row + 8) * N + col]) =
                        make_float2(acc[mi][ni][2], acc[mi][ni][3]);
            }
        }
    }
}

// ---------------------------------------------------------------------------
// CSR SpMM (exact R6 versions): warp per node, fp16 gathers, fp32 accumulate,
// fused bias+ReLU. F=128: lane owns 4 features (uint2 per gather).
// ---------------------------------------------------------------------------
__global__ __launch_bounds__(256) void spmm_f16_128(
    const float* __restrict__ vals, const int* __restrict__ cols,
    const int* __restrict__ rp, const uint2* __restrict__ Hv,
    const float4* __restrict__ bias4, float4* __restrict__ out4) {
    int node = blockIdx.x * 8 + (threadIdx.x >> 5);
    int lane = threadIdx.x & 31;
    if (node >= N_NODES) return;
    int s = rp[node], e = rp[node + 1];

    const uint2* __restrict__ Hl = Hv + lane;   // row stride 32 uint2

    float4 acc = make_float4(0.f, 0.f, 0.f, 0.f);

    auto accum = [&](int c, float v) {
        uint2 u = __ldg(&Hl[(size_t)c * 32]);
        float2 f0 = __half22float2(*reinterpret_cast<__half2*>(&u.x));
        float2 f1 = __half22float2(*reinterpret_cast<__half2*>(&u.y));
        acc.x = fmaf(v, f0.x, acc.x); acc.y = fmaf(v, f0.y, acc.y);
        acc.z = fmaf(v, f1.x, acc.z); acc.w = fmaf(v, f1.y, acc.w);
    };

    int i = s;
    for (; i < e && (i & 3); i++) accum(__ldg(&cols[i]), __ldg(&vals[i]));
    for (; i + 4 <= e; i += 4) {
        int4   c4 = __ldg(reinterpret_cast<const int4*>(&cols[i]));
        float4 v4 = __ldg(reinterpret_cast<const float4*>(&vals[i]));
        accum(c4.x, v4.x);
        accum(c4.y, v4.y);
        accum(c4.z, v4.z);
        accum(c4.w, v4.w);
    }
    for (; i < e; i++) accum(__ldg(&cols[i]), __ldg(&vals[i]));

    float4 b = bias4[lane];
    acc.x = fmaxf(acc.x + b.x, 0.f);
    acc.y = fmaxf(acc.y + b.y, 0.f);
    acc.z = fmaxf(acc.z + b.z, 0.f);
    acc.w = fmaxf(acc.w + b.w, 0.f);
    out4[(size_t)node * 32 + lane] = acc;
}

// F=64: lane owns 2 features (one half2 per gather).
__global__ __launch_bounds__(256) void spmm_f16_64(
    const float* __restrict__ vals, const int* __restrict__ cols,
    const int* __restrict__ rp, const uint32_t* __restrict__ Hv,
    const float2* __restrict__ bias2, float2* __restrict__ out2) {
    int node = blockIdx.x * 8 + (threadIdx.x >> 5);
    int lane = threadIdx.x & 31;
    if (node >= N_NODES) return;
    int s = rp[node], e = rp[node + 1];

    const uint32_t* __restrict__ Hl = Hv + lane;  // row stride 32 half2

    float2 acc = make_float2(0.f, 0.f);

    auto accum = [&](int c, float v) {
        uint32_t u = __ldg(&Hl[(size_t)c * 32]);
        float2 f = __half22float2(*reinterpret_cast<__half2*>(&u));
        acc.x = fmaf(v, f.x, acc.x);
        acc.y = fmaf(v, f.y, acc.y);
    };

    int i = s;
    for (; i < e && (i & 3); i++) accum(__ldg(&cols[i]), __ldg(&vals[i]));
    for (; i + 4 <= e; i += 4) {
        int4   c4 = __ldg(reinterpret_cast<const int4*>(&cols[i]));
        float4 v4 = __ldg(reinterpret_cast<const float4*>(&vals[i]));
        accum(c4.x, v4.x);
        accum(c4.y, v4.y);
        accum(c4.z, v4.z);
        accum(c4.w, v4.w);
    }
    for (; i < e; i++) accum(__ldg(&cols[i]), __ldg(&vals[i]));

    float2 b = bias2[lane];
    acc.x = fmaxf(acc.x + b.x, 0.f);
    acc.y = fmaxf(acc.y + b.y, 0.f);
    out2[(size_t)node * 32 + lane] = acc;
}

// ---------------------------------------------------------------------------
extern "C" void kernel_launch(void* const* d_in, const int* in_sizes, int n_in,
                              void* d_out, int out_size) {
    const float* x     = (const float*)d_in[0];
    const float* W1    = (const float*)d_in[1];
    const float* b1    = (const float*)d_in[2];
    const float* W2    = (const float*)d_in[3];
    const float* b2    = (const float*)d_in[4];
    const float* evals = (const float*)d_in[5];
    const int*   erows = (const int*)d_in[6];
    const int*   ecols = (const int*)d_in[7];
    float*       out   = (float*)d_out;

    const int E = in_sizes[5];

    void *pH0, *pH1, *pH2, *pRP;
    cudaGetSymbolAddress(&pH0, g_H0h);
    cudaGetSymbolAddress(&pH1, g_H1);
    cudaGetSymbolAddress(&pH2, g_H2h);
    cudaGetSymbolAddress(&pRP, g_rowptr);
    __half* H0h = (__half*)pH0;
    float*  H1  = (float*)pH1;
    __half* H2h = (__half*)pH2;
    int*    rp  = (int*)pRP;

    const int SPMM_GRID = (N_NODES + 7) / 8;

    // row_ptr from sorted rows
    rowptr_kernel<<<(N_NODES + 1 + 255) / 256, 256>>>(erows, E, rp);

    // GEMM1: H0h = fp16(x @ W1)   (M=100000, N=128, K=256)
    {
        dim3 grid((N_NODES + GBM - 1) / GBM, NHID / GBN);
        gemm_f16_kernel<true><<<grid, 256>>>(x, W1, H0h, N_NODES, NHID, NFEAT);
    }

    // SpMM1: H1 = relu(A @ H0 + b1)
    spmm_f16_128<<<SPMM_GRID, 256>>>(evals, ecols, rp, (const uint2*)H0h,
                                     (const float4*)b1, (float4*)H1);

    // GEMM2: H2h = fp16(H1 @ W2)   (M=100000, N=64, K=128)
    {
        dim3 grid((N_NODES + GBM - 1) / GBM, NHID2 / GBN);
        gemm_f16_kernel<true><<<grid, 256>>>(H1, W2, H2h, N_NODES, NHID2, NHID);
    }

    // SpMM2: out = relu(A @ H2 + b2)
    spmm_f16_64<<<SPMM_GRID, 256>>>(evals, ecols, rp, (const uint32_t*)H2h,
                                    (const float2*)b2, (float2*)out);
}

// round 9
// speedup vs baseline: 1.5622x; 1.0101x over previous
#include <cuda_runtime.h>
#include <cuda_fp16.h>
#include <cstdint>

#define N_NODES 100000
#define NFEAT   256
#define NHID    128
#define NHID2   64

// Scratch (no cudaMalloc allowed). H0/H2 stored as fp16 (halves gather bytes).
__device__ __half g_H0h[(size_t)N_NODES * NHID];   // fp16(x @ W1)
__device__ float  g_H1[(size_t)N_NODES * NHID];    // relu(spmm(A,H0)+b1)  fp32
__device__ __half g_H2h[(size_t)N_NODES * NHID2];  // fp16(H1 @ W2)
__device__ int    g_rowptr[N_NODES + 1];

// ---------------------------------------------------------------------------
// row_ptr from sorted COO rows: rp[i] = lower_bound(rows, i)
// ---------------------------------------------------------------------------
__global__ void rowptr_kernel(const int* __restrict__ rows, int E,
                              int* __restrict__ rp) {
    int i = blockIdx.x * blockDim.x + threadIdx.x;
    if (i > N_NODES) return;
    int lo = 0, hi = E;
    while (lo < hi) {
        int mid = (lo + hi) >> 1;
        if (rows[mid] < i) lo = mid + 1; else hi = mid;
    }
    rp[i] = lo;
}

// ---------------------------------------------------------------------------
// fp16 tensor-core GEMM: C = A @ B, fp32 in (converted to fp16 at staging),
// fp32 accumulate. mma.m16n8k16. Tile BM=128 x BN=64, BK=32, 256 threads,
// warps 4(m) x 2(n), each warp computes 32x32.
// As: [GBM][APITCH] halves row-major-in-k; Bst: [GBN][BPITCH] halves
// (B transposed at staging so k is contiguous). APITCH=BPITCH=40 halves
// -> LDS word index row*20+t covers all 32 banks, conflict-free.
// HALF_OUT: store fp16 (for SpMM gathers), else fp32.
// ---------------------------------------------------------------------------
#define GBM 128
#define GBN 64
#define GBK 32
#define HPITCH 40

__device__ __forceinline__ void mma_f16(float* d, const uint32_t* a,
                                        const uint32_t* b) {
    asm("mma.sync.aligned.m16n8k16.row.col.f32.f16.f16.f32 "
        "{%0,%1,%2,%3},{%4,%5,%6,%7},{%8,%9},{%0,%1,%2,%3};"
        : "+f"(d[0]), "+f"(d[1]), "+f"(d[2]), "+f"(d[3])
        : "r"(a[0]), "r"(a[1]), "r"(a[2]), "r"(a[3]), "r"(b[0]), "r"(b[1]));
}

template <bool HALF_OUT>
__global__ __launch_bounds__(256) void gemm_f16_kernel(
    const float* __restrict__ A, const float* __restrict__ B,
    void* __restrict__ Cv, int M, int N, int K) {
    __shared__ __half As[GBM * HPITCH];
    __shared__ __half Bst[GBN * HPITCH];

    const int tid  = threadIdx.x;
    const int wid  = tid >> 5, lane = tid & 31;
    const int g    = lane >> 2, tig = lane & 3;
    const int warp_m = wid >> 1, warp_n = wid & 1;
    const int mBase = blockIdx.x * GBM;
    const int nBase = blockIdx.y * GBN;
    const int KT = K / GBK;

    float acc[2][4][4];
#pragma unroll
    for (int mi = 0; mi < 2; mi++)
#pragma unroll
        for (int ni = 0; ni < 4; ni++)
#pragma unroll
            for (int r = 0; r < 4; r++) acc[mi][ni][r] = 0.f;

    float4 aReg[4], bReg[2];

    auto loadTile = [&](int kt) {
#pragma unroll
        for (int i = 0; i < 4; i++) {
            int idx = tid + i * 256;
            int row = idx >> 3, kc = (idx & 7) << 2;
            int grow = mBase + row;
            float4 v = make_float4(0.f, 0.f, 0.f, 0.f);
            if (grow < M)
                v = *reinterpret_cast<const float4*>(
                        &A[(size_t)grow * K + kt * GBK + kc]);
            aReg[i] = v;
        }
#pragma unroll
        for (int i = 0; i < 2; i++) {
            int idx = tid + i * 256;
            int kr = idx >> 4, nc = (idx & 15) << 2;
            bReg[i] = *reinterpret_cast<const float4*>(
                          &B[(size_t)(kt * GBK + kr) * N + nBase + nc]);
        }
    };
    auto stageTile = [&]() {
        // A: row-major in k, 4 contiguous halves per thread-chunk (8B store)
#pragma unroll
        for (int i = 0; i < 4; i++) {
            int idx = tid + i * 256;
            int row = idx >> 3, kc = (idx & 7) << 2;
            float4 v = aReg[i];
            __half2 h01 = __floats2half2_rn(v.x, v.y);
            __half2 h23 = __floats2half2_rn(v.z, v.w);
            uint2 pk = make_uint2(*reinterpret_cast<uint32_t*>(&h01),
                                  *reinterpret_cast<uint32_t*>(&h23));
            *reinterpret_cast<uint2*>(&As[row * HPITCH + kc]) = pk;
        }
        // B: transpose to [n][k] halves (4 scalar stores per float4)
#pragma unroll
        for (int i = 0; i < 2; i++) {
            int idx = tid + i * 256;
            int kr = idx >> 4, nc = (idx & 15) << 2;
            float4 v = bReg[i];
            Bst[(nc + 0) * HPITCH + kr] = __float2half_rn(v.x);
            Bst[(nc + 1) * HPITCH + kr] = __float2half_rn(v.y);
            Bst[(nc + 2) * HPITCH + kr] = __float2half_rn(v.z);
            Bst[(nc + 3) * HPITCH + kr] = __float2half_rn(v.w);
        }
    };

    loadTile(0);
    stageTile();
    __syncthreads();

    for (int kt = 0; kt < KT; kt++) {
        if (kt + 1 < KT) loadTile(kt + 1);

#pragma unroll
        for (int ka = 0; ka < 2; ka++) {            // two k16 chunks per BK=32
            const int k0 = ka * 16 + 2 * tig;
            uint32_t a[2][4], b[4][2];
#pragma unroll
            for (int mi = 0; mi < 2; mi++) {
                int row = warp_m * 32 + mi * 16 + g;
                a[mi][0] = *reinterpret_cast<const uint32_t*>(&As[row * HPITCH + k0]);
                a[mi][1] = *reinterpret_cast<const uint32_t*>(&As[(row + 8) * HPITCH + k0]);
                a[mi][2] = *reinterpret_cast<const uint32_t*>(&As[row * HPITCH + k0 + 8]);
                a[mi][3] = *reinterpret_cast<const uint32_t*>(&As[(row + 8) * HPITCH + k0 + 8]);
            }
#pragma unroll
            for (int ni = 0; ni < 4; ni++) {
                int col = warp_n * 32 + ni * 8 + g;
                b[ni][0] = *reinterpret_cast<const uint32_t*>(&Bst[col * HPITCH + k0]);
                b[ni][1] = *reinterpret_cast<const uint32_t*>(&Bst[col * HPITCH + k0 + 8]);
            }
#pragma unroll
            for (int mi = 0; mi < 2; mi++)
#pragma unroll
                for (int ni = 0; ni < 4; ni++)
                    mma_f16(acc[mi][ni], a[mi], b[ni]);
        }
        __syncthreads();
        if (kt + 1 < KT) {
            stageTile();
            __syncthreads();
        }
    }

    // store (same accumulator layout as m16n8k8 f32)
#pragma unroll
    for (int mi = 0; mi < 2; mi++) {
        int row = mBase + warp_m * 32 + mi * 16 + g;
#pragma unroll
        for (int ni = 0; ni < 4; ni++) {
            int col = nBase + warp_n * 32 + ni * 8 + 2 * tig;
            if (HALF_OUT) {
                __half* C16 = (__half*)Cv;
                if (row < M)
                    *reinterpret_cast<__half2*>(&C16[(size_t)row * N + col]) =
                        __floats2half2_rn(acc[mi][ni][0], acc[mi][ni][1]);
                if (row + 8 < M)
                    *reinterpret_cast<__half2*>(&C16[(size_t)(row + 8) * N + col]) =
                        __floats2half2_rn(acc[mi][ni][2], acc[mi][ni][3]);
            } else {
                float* C = (float*)Cv;
                if (row < M)
                    *reinterpret_cast<float2*>(&C[(size_t)row * N + col]) =
                        make_float2(acc[mi][ni][0], acc[mi][ni][1]);
                if (row + 8 < M)
                    *reinterpret_cast<float2*>(&C[(size_t)(row + 8) * N + col]) =
                        make_float2(acc[mi][ni][2], acc[mi][ni][3]);
            }
        }
    }
}

// ---------------------------------------------------------------------------
// CSR SpMM (exact R6 versions): warp per node, fp16 gathers, fp32 accumulate,
// fused bias+ReLU. F=128: lane owns 4 features (uint2 per gather).
// ---------------------------------------------------------------------------
__global__ __launch_bounds__(256) void spmm_f16_128(
    const float* __restrict__ vals, const int* __restrict__ cols,
    const int* __restrict__ rp, const uint2* __restrict__ Hv,
    const float4* __restrict__ bias4, float4* __restrict__ out4) {
    int node = blockIdx.x * 8 + (threadIdx.x >> 5);
    int lane = threadIdx.x & 31;
    if (node >= N_NODES) return;
    int s = rp[node], e = rp[node + 1];

    const uint2* __restrict__ Hl = Hv + lane;   // row stride 32 uint2

    float4 acc = make_float4(0.f, 0.f, 0.f, 0.f);

    auto accum = [&](int c, float v) {
        uint2 u = __ldg(&Hl[(size_t)c * 32]);
        float2 f0 = __half22float2(*reinterpret_cast<__half2*>(&u.x));
        float2 f1 = __half22float2(*reinterpret_cast<__half2*>(&u.y));
        acc.x = fmaf(v, f0.x, acc.x); acc.y = fmaf(v, f0.y, acc.y);
        acc.z = fmaf(v, f1.x, acc.z); acc.w = fmaf(v, f1.y, acc.w);
    };

    int i = s;
    for (; i < e && (i & 3); i++) accum(__ldg(&cols[i]), __ldg(&vals[i]));
    for (; i + 4 <= e; i += 4) {
        int4   c4 = __ldg(reinterpret_cast<const int4*>(&cols[i]));
        float4 v4 = __ldg(reinterpret_cast<const float4*>(&vals[i]));
        accum(c4.x, v4.x);
        accum(c4.y, v4.y);
        accum(c4.z, v4.z);
        accum(c4.w, v4.w);
    }
    for (; i < e; i++) accum(__ldg(&cols[i]), __ldg(&vals[i]));

    float4 b = bias4[lane];
    acc.x = fmaxf(acc.x + b.x, 0.f);
    acc.y = fmaxf(acc.y + b.y, 0.f);
    acc.z = fmaxf(acc.z + b.z, 0.f);
    acc.w = fmaxf(acc.w + b.w, 0.f);
    out4[(size_t)node * 32 + lane] = acc;
}

// F=64: lane owns 2 features (one half2 per gather).
__global__ __launch_bounds__(256) void spmm_f16_64(
    const float* __restrict__ vals, const int* __restrict__ cols,
    const int* __restrict__ rp, const uint32_t* __restrict__ Hv,
    const float2* __restrict__ bias2, float2* __restrict__ out2) {
    int node = blockIdx.x * 8 + (threadIdx.x >> 5);
    int lane = threadIdx.x & 31;
    if (node >= N_NODES) return;
    int s = rp[node], e = rp[node + 1];

    const uint32_t* __restrict__ Hl = Hv + lane;  // row stride 32 half2

    float2 acc = make_float2(0.f, 0.f);

    auto accum = [&](int c, float v) {
        uint32_t u = __ldg(&Hl[(size_t)c * 32]);
        float2 f = __half22float2(*reinterpret_cast<__half2*>(&u));
        acc.x = fmaf(v, f.x, acc.x);
        acc.y = fmaf(v, f.y, acc.y);
    };

    int i = s;
    for (; i < e && (i & 3); i++) accum(__ldg(&cols[i]), __ldg(&vals[i]));
    for (; i + 4 <= e; i += 4) {
        int4   c4 = __ldg(reinterpret_cast<const int4*>(&cols[i]));
        float4 v4 = __ldg(reinterpret_cast<const float4*>(&vals[i]));
        accum(c4.x, v4.x);
        accum(c4.y, v4.y);
        accum(c4.z, v4.z);
        accum(c4.w, v4.w);
    }
    for (; i < e; i++) accum(__ldg(&cols[i]), __ldg(&vals[i]));

    float2 b = bias2[lane];
    acc.x = fmaxf(acc.x + b.x, 0.f);
    acc.y = fmaxf(acc.y + b.y, 0.f);
    out2[(size_t)node * 32 + lane] = acc;
}

// ---------------------------------------------------------------------------
extern "C" void kernel_launch(void* const* d_in, const int* in_sizes, int n_in,
                              void* d_out, int out_size) {
    const float* x     = (const float*)d_in[0];
    const float* W1    = (const float*)d_in[1];
    const float* b1    = (const float*)d_in[2];
    const float* W2    = (const float*)d_in[3];
    const float* b2    = (const float*)d_in[4];
    const float* evals = (const float*)d_in[5];
    const int*   erows = (const int*)d_in[6];
    const int*   ecols = (const int*)d_in[7];
    float*       out   = (float*)d_out;

    const int E = in_sizes[5];

    void *pH0, *pH1, *pH2, *pRP;
    cudaGetSymbolAddress(&pH0, g_H0h);
    cudaGetSymbolAddress(&pH1, g_H1);
    cudaGetSymbolAddress(&pH2, g_H2h);
    cudaGetSymbolAddress(&pRP, g_rowptr);
    __half* H0h = (__half*)pH0;
    float*  H1  = (float*)pH1;
    __half* H2h = (__half*)pH2;
    int*    rp  = (int*)pRP;

    const int SPMM_GRID = (N_NODES + 7) / 8;

    // row_ptr from sorted rows
    rowptr_kernel<<<(N_NODES + 1 + 255) / 256, 256>>>(erows, E, rp);

    // GEMM1: H0h = fp16(x @ W1)   (M=100000, N=128, K=256)
    {
        dim3 grid((N_NODES + GBM - 1) / GBM, NHID / GBN);
        gemm_f16_kernel<true><<<grid, 256>>>(x, W1, H0h, N_NODES, NHID, NFEAT);
    }

    // SpMM1: H1 = relu(A @ H0 + b1)
    spmm_f16_128<<<SPMM_GRID, 256>>>(evals, ecols, rp, (const uint2*)H0h,
                                     (const float4*)b1, (float4*)H1);

    // GEMM2: H2h = fp16(H1 @ W2)   (M=100000, N=64, K=128)
    {
        dim3 grid((N_NODES + GBM - 1) / GBM, NHID2 / GBN);
        gemm_f16_kernel<true><<<grid, 256>>>(H1, W2, H2h, N_NODES, NHID2, NHID);
    }

    // SpMM2: out = relu(A @ H2 + b2)
    spmm_f16_64<<<SPMM_GRID, 256>>>(evals, ecols, rp, (const uint32_t*)H2h,
                                    (const float2*)b2, (float2*)out);
}

// round 10
// speedup vs baseline: 1.5627x; 1.0003x over previous
#include <cuda_runtime.h>
#include <cuda_fp16.h>
#include <cstdint>

#define N_NODES 100000
#define NFEAT   256
#define NHID    128
#define NHID2   64

// Scratch (no cudaMalloc allowed). H0/H2 stored as fp16 (halves gather bytes).
__device__ __half g_H0h[(size_t)N_NODES * NHID];   // fp16(x @ W1)
__device__ float  g_H1[(size_t)N_NODES * NHID];    // relu(spmm(A,H0)+b1)  fp32
__device__ __half g_H2h[(size_t)N_NODES * NHID2];  // fp16(H1 @ W2)
__device__ int    g_rowptr[N_NODES + 1];

// ---------------------------------------------------------------------------
// row_ptr from sorted COO rows: rp[i] = lower_bound(rows, i)
// ---------------------------------------------------------------------------
__global__ void rowptr_kernel(const int* __restrict__ rows, int E,
                              int* __restrict__ rp) {
    int i = blockIdx.x * blockDim.x + threadIdx.x;
    if (i > N_NODES) return;
    int lo = 0, hi = E;
    while (lo < hi) {
        int mid = (lo + hi) >> 1;
        if (rows[mid] < i) lo = mid + 1; else hi = mid;
    }
    rp[i] = lo;
}

// ---------------------------------------------------------------------------
// fp16 tensor-core GEMM: C = A @ B, fp32 in (converted to fp16 at staging),
// fp32 accumulate. mma.m16n8k16. Tile BM=128 x BN=64, BK=32, 256 threads,
// warps 4(m) x 2(n), each warp computes 32x32.
// As: [GBM][APITCH] halves row-major-in-k; Bst: [GBN][BPITCH] halves
// (B transposed at staging so k is contiguous). APITCH=BPITCH=40 halves
// -> LDS word index row*20+t covers all 32 banks, conflict-free.
// HALF_OUT: store fp16 (for SpMM gathers), else fp32.
// ---------------------------------------------------------------------------
#define GBM 128
#define GBN 64
#define GBK 32
#define HPITCH 40

__device__ __forceinline__ void mma_f16(float* d, const uint32_t* a,
                                        const uint32_t* b) {
    asm("mma.sync.aligned.m16n8k16.row.col.f32.f16.f16.f32 "
        "{%0,%1,%2,%3},{%4,%5,%6,%7},{%8,%9},{%0,%1,%2,%3};"
        : "+f"(d[0]), "+f"(d[1]), "+f"(d[2]), "+f"(d[3])
        : "r"(a[0]), "r"(a[1]), "r"(a[2]), "r"(a[3]), "r"(b[0]), "r"(b[1]));
}

template <bool HALF_OUT>
__global__ __launch_bounds__(256) void gemm_f16_kernel(
    const float* __restrict__ A, const float* __restrict__ B,
    void* __restrict__ Cv, int M, int N, int K) {
    __shared__ __half As[GBM * HPITCH];
    __shared__ __half Bst[GBN * HPITCH];

    const int tid  = threadIdx.x;
    const int wid  = tid >> 5, lane = tid & 31;
    const int g    = lane >> 2, tig = lane & 3;
    const int warp_m = wid >> 1, warp_n = wid & 1;
    const int mBase = blockIdx.x * GBM;
    const int nBase = blockIdx.y * GBN;
    const int KT = K / GBK;

    float acc[2][4][4];
#pragma unroll
    for (int mi = 0; mi < 2; mi++)
#pragma unroll
        for (int ni = 0; ni < 4; ni++)
#pragma unroll
            for (int r = 0; r < 4; r++) acc[mi][ni][r] = 0.f;

    float4 aReg[4], bReg[2];

    auto loadTile = [&](int kt) {
#pragma unroll
        for (int i = 0; i < 4; i++) {
            int idx = tid + i * 256;
            int row = idx >> 3, kc = (idx & 7) << 2;
            int grow = mBase + row;
            float4 v = make_float4(0.f, 0.f, 0.f, 0.f);
            if (grow < M)
                v = *reinterpret_cast<const float4*>(
                        &A[(size_t)grow * K + kt * GBK + kc]);
            aReg[i] = v;
        }
#pragma unroll
        for (int i = 0; i < 2; i++) {
            int idx = tid + i * 256;
            int kr = idx >> 4, nc = (idx & 15) << 2;
            bReg[i] = *reinterpret_cast<const float4*>(
                          &B[(size_t)(kt * GBK + kr) * N + nBase + nc]);
        }
    };
    auto stageTile = [&]() {
        // A: row-major in k, 4 contiguous halves per thread-chunk (8B store)
#pragma unroll
        for (int i = 0; i < 4; i++) {
            int idx = tid + i * 256;
            int row = idx >> 3, kc = (idx & 7) << 2;
            float4 v = aReg[i];
            __half2 h01 = __floats2half2_rn(v.x, v.y);
            __half2 h23 = __floats2half2_rn(v.z, v.w);
            uint2 pk = make_uint2(*reinterpret_cast<uint32_t*>(&h01),
                                  *reinterpret_cast<uint32_t*>(&h23));
            *reinterpret_cast<uint2*>(&As[row * HPITCH + kc]) = pk;
        }
        // B: transpose to [n][k] halves (4 scalar stores per float4)
#pragma unroll
        for (int i = 0; i < 2; i++) {
            int idx = tid + i * 256;
            int kr = idx >> 4, nc = (idx & 15) << 2;
            float4 v = bReg[i];
            Bst[(nc + 0) * HPITCH + kr] = __float2half_rn(v.x);
            Bst[(nc + 1) * HPITCH + kr] = __float2half_rn(v.y);
            Bst[(nc + 2) * HPITCH + kr] = __float2half_rn(v.z);
            Bst[(nc + 3) * HPITCH + kr] = __float2half_rn(v.w);
        }
    };

    loadTile(0);
    stageTile();
    __syncthreads();

    for (int kt = 0; kt < KT; kt++) {
        if (kt + 1 < KT) loadTile(kt + 1);

#pragma unroll
        for (int ka = 0; ka < 2; ka++) {            // two k16 chunks per BK=32
            const int k0 = ka * 16 + 2 * tig;
            uint32_t a[2][4], b[4][2];
#pragma unroll
            for (int mi = 0; mi < 2; mi++) {
                int row = warp_m * 32 + mi * 16 + g;
                a[mi][0] = *reinterpret_cast<const uint32_t*>(&As[row * HPITCH + k0]);
                a[mi][1] = *reinterpret_cast<const uint32_t*>(&As[(row + 8) * HPITCH + k0]);
                a[mi][2] = *reinterpret_cast<const uint32_t*>(&As[row * HPITCH + k0 + 8]);
                a[mi][3] = *reinterpret_cast<const uint32_t*>(&As[(row + 8) * HPITCH + k0 + 8]);
            }
#pragma unroll
            for (int ni = 0; ni < 4; ni++) {
                int col = warp_n * 32 + ni * 8 + g;
                b[ni][0] = *reinterpret_cast<const uint32_t*>(&Bst[col * HPITCH + k0]);
                b[ni][1] = *reinterpret_cast<const uint32_t*>(&Bst[col * HPITCH + k0 + 8]);
            }
#pragma unroll
            for (int mi = 0; mi < 2; mi++)
#pragma unroll
                for (int ni = 0; ni < 4; ni++)
                    mma_f16(acc[mi][ni], a[mi], b[ni]);
        }
        __syncthreads();
        if (kt + 1 < KT) {
            stageTile();
            __syncthreads();
        }
    }

    // store (same accumulator layout as m16n8k8 f32)
#pragma unroll
    for (int mi = 0; mi < 2; mi++) {
        int row = mBase + warp_m * 32 + mi * 16 + g;
#pragma unroll
        for (int ni = 0; ni < 4; ni++) {
            int col = nBase + warp_n * 32 + ni * 8 + 2 * tig;
            if (HALF_OUT) {
                __half* C16 = (__half*)Cv;
                if (row < M)
                    *reinterpret_cast<__half2*>(&C16[(size_t)row * N + col]) =
                        __floats2half2_rn(acc[mi][ni][0], acc[mi][ni][1]);
                if (row + 8 < M)
                    *reinterpret_cast<__half2*>(&C16[(size_t)(row + 8) * N + col]) =
                        __floats2half2_rn(acc[mi][ni][2], acc[mi][ni][3]);
            } else {
                float* C = (float*)Cv;
                if (row < M)
                    *reinterpret_cast<float2*>(&C[(size_t)row * N + col]) =
                        make_float2(acc[mi][ni][0], acc[mi][ni][1]);
                if (row + 8 < M)
                    *reinterpret_cast<float2*>(&C[(size_t)(row + 8) * N + col]) =
                        make_float2(acc[mi][ni][2], acc[mi][ni][3]);
            }
        }
    }
}

// ---------------------------------------------------------------------------
// CSR SpMM (exact R6 versions): warp per node, fp16 gathers, fp32 accumulate,
// fused bias+ReLU. F=128: lane owns 4 features (uint2 per gather).
// ---------------------------------------------------------------------------
__global__ __launch_bounds__(256) void spmm_f16_128(
    const float* __restrict__ vals, const int* __restrict__ cols,
    const int* __restrict__ rp, const uint2* __restrict__ Hv,
    const float4* __restrict__ bias4, float4* __restrict__ out4) {
    int node = blockIdx.x * 8 + (threadIdx.x >> 5);
    int lane = threadIdx.x & 31;
    if (node >= N_NODES) return;
    int s = rp[node], e = rp[node + 1];

    const uint2* __restrict__ Hl = Hv + lane;   // row stride 32 uint2

    float4 acc = make_float4(0.f, 0.f, 0.f, 0.f);

    auto accum = [&](int c, float v) {
        uint2 u = __ldg(&Hl[(size_t)c * 32]);
        float2 f0 = __half22float2(*reinterpret_cast<__half2*>(&u.x));
        float2 f1 = __half22float2(*reinterpret_cast<__half2*>(&u.y));
        acc.x = fmaf(v, f0.x, acc.x); acc.y = fmaf(v, f0.y, acc.y);
        acc.z = fmaf(v, f1.x, acc.z); acc.w = fmaf(v, f1.y, acc.w);
    };

    int i = s;
    for (; i < e && (i & 3); i++) accum(__ldg(&cols[i]), __ldg(&vals[i]));
    for (; i + 4 <= e; i += 4) {
        int4   c4 = __ldg(reinterpret_cast<const int4*>(&cols[i]));
        float4 v4 = __ldg(reinterpret_cast<const float4*>(&vals[i]));
        accum(c4.x, v4.x);
        accum(c4.y, v4.y);
        accum(c4.z, v4.z);
        accum(c4.w, v4.w);
    }
    for (; i < e; i++) accum(__ldg(&cols[i]), __ldg(&vals[i]));

    float4 b = bias4[lane];
    acc.x = fmaxf(acc.x + b.x, 0.f);
    acc.y = fmaxf(acc.y + b.y, 0.f);
    acc.z = fmaxf(acc.z + b.z, 0.f);
    acc.w = fmaxf(acc.w + b.w, 0.f);
    out4[(size_t)node * 32 + lane] = acc;
}

// F=64: lane owns 2 features (one half2 per gather).
__global__ __launch_bounds__(256) void spmm_f16_64(
    const float* __restrict__ vals, const int* __restrict__ cols,
    const int* __restrict__ rp, const uint32_t* __restrict__ Hv,
    const float2* __restrict__ bias2, float2* __restrict__ out2) {
    int node = blockIdx.x * 8 + (threadIdx.x >> 5);
    int lane = threadIdx.x & 31;
    if (node >= N_NODES) return;
    int s = rp[node], e = rp[node + 1];

    const uint32_t* __restrict__ Hl = Hv + lane;  // row stride 32 half2

    float2 acc = make_float2(0.f, 0.f);

    auto accum = [&](int c, float v) {
        uint32_t u = __ldg(&Hl[(size_t)c * 32]);
        float2 f = __half22float2(*reinterpret_cast<__half2*>(&u));
        acc.x = fmaf(v, f.x, acc.x);
        acc.y = fmaf(v, f.y, acc.y);
    };

    int i = s;
    for (; i < e && (i & 3); i++) accum(__ldg(&cols[i]), __ldg(&vals[i]));
    for (; i + 4 <= e; i += 4) {
        int4   c4 = __ldg(reinterpret_cast<const int4*>(&cols[i]));
        float4 v4 = __ldg(reinterpret_cast<const float4*>(&vals[i]));
        accum(c4.x, v4.x);
        accum(c4.y, v4.y);
        accum(c4.z, v4.z);
        accum(c4.w, v4.w);
    }
    for (; i < e; i++) accum(__ldg(&cols[i]), __ldg(&vals[i]));

    float2 b = bias2[lane];
    acc.x = fmaxf(acc.x + b.x, 0.f);
    acc.y = fmaxf(acc.y + b.y, 0.f);
    out2[(size_t)node * 32 + lane] = acc;
}

// ---------------------------------------------------------------------------
extern "C" void kernel_launch(void* const* d_in, const int* in_sizes, int n_in,
                              void* d_out, int out_size) {
    const float* x     = (const float*)d_in[0];
    const float* W1    = (const float*)d_in[1];
    const float* b1    = (const float*)d_in[2];
    const float* W2    = (const float*)d_in[3];
    const float* b2    = (const float*)d_in[4];
    const float* evals = (const float*)d_in[5];
    const int*   erows = (const int*)d_in[6];
    const int*   ecols = (const int*)d_in[7];
    float*       out   = (float*)d_out;

    const int E = in_sizes[5];

    void *pH0, *pH1, *pH2, *pRP;
    cudaGetSymbolAddress(&pH0, g_H0h);
    cudaGetSymbolAddress(&pH1, g_H1);
    cudaGetSymbolAddress(&pH2, g_H2h);
    cudaGetSymbolAddress(&pRP, g_rowptr);
    __half* H0h = (__half*)pH0;
    float*  H1  = (float*)pH1;
    __half* H2h = (__half*)pH2;
    int*    rp  = (int*)pRP;

    const int SPMM_GRID = (N_NODES + 7) / 8;

    // row_ptr from sorted rows
    rowptr_kernel<<<(N_NODES + 1 + 255) / 256, 256>>>(erows, E, rp);

    // GEMM1: H0h = fp16(x @ W1)   (M=100000, N=128, K=256)
    {
        dim3 grid((N_NODES + GBM - 1) / GBM, NHID / GBN);
        gemm_f16_kernel<true><<<grid, 256>>>(x, W1, H0h, N_NODES, NHID, NFEAT);
    }

    // SpMM1: H1 = relu(A @ H0 + b1)
    spmm_f16_128<<<SPMM_GRID, 256>>>(evals, ecols, rp, (const uint2*)H0h,
                                     (const float4*)b1, (float4*)H1);

    // GEMM2: H2h = fp16(H1 @ W2)   (M=100000, N=64, K=128)
    {
        dim3 grid((N_NODES + GBM - 1) / GBM, NHID2 / GBN);
        gemm_f16_kernel<true><<<grid, 256>>>(H1, W2, H2h, N_NODES, NHID2, NHID);
    }

    // SpMM2: out = relu(A @ H2 + b2)
    spmm_f16_64<<<SPMM_GRID, 256>>>(evals, ecols, rp, (const uint32_t*)H2h,
                                    (const float2*)b2, (float2*)out);
}